// round 15
// baseline (speedup 1.0000x reference)
#include <cuda_runtime.h>
#include <cuda_bf16.h>
#include <math.h>
#include <stdint.h>

#define B_ROWS   8192
#define M_DIM    512
#define N_DIM    2048
#define IN_COLS  4608
#define OUT_COLS 8704
#define THETA    0.1f
#define KTH      103

// ---- scratch: planar bf16 hi/lo operands -----------------------------------
__device__ __align__(16) unsigned char g_gxh [33554432]; // 8192x2048 bf16
__device__ __align__(16) unsigned char g_gxl [33554432];
__device__ __align__(16) unsigned char g_Ah  [2097152];  // 512x2048
__device__ __align__(16) unsigned char g_Al  [2097152];
__device__ __align__(16) unsigned char g_Wth [2097152];  // Wt: 2048x512
__device__ __align__(16) unsigned char g_Wtl [2097152];
__device__ __align__(16) unsigned char g_resh[8388608];  // 8192x512
__device__ __align__(16) unsigned char g_resl[8388608];
__device__ float g_zk[(size_t)B_ROWS * N_DIM];

// ---- helpers ----------------------------------------------------------------
__device__ __forceinline__ uint32_t smem_u32(const void* p) {
    uint32_t a;
    asm("{ .reg .u64 t; cvta.to.shared.u64 t, %1; cvt.u32.u64 %0, t; }" : "=r"(a) : "l"(p));
    return a;
}
__device__ __forceinline__ void cpa(uint32_t dst, const void* src) {
    asm volatile("cp.async.cg.shared.global [%0], [%1], 16;" :: "r"(dst), "l"(src));
}
__device__ __forceinline__ void ldsm4(uint32_t* r, uint32_t a) {
    asm volatile("ldmatrix.sync.aligned.m8n8.x4.shared.b16 {%0,%1,%2,%3}, [%4];"
                 : "=r"(r[0]), "=r"(r[1]), "=r"(r[2]), "=r"(r[3]) : "r"(a));
}
__device__ __forceinline__ void mma16816(float* c, const uint32_t* a, const uint32_t* b) {
    asm volatile(
        "mma.sync.aligned.m16n8k16.row.col.f32.bf16.bf16.f32 "
        "{%0,%1,%2,%3}, {%4,%5,%6,%7}, {%8,%9}, {%0,%1,%2,%3};"
        : "+f"(c[0]), "+f"(c[1]), "+f"(c[2]), "+f"(c[3])
        : "r"(a[0]), "r"(a[1]), "r"(a[2]), "r"(a[3]), "r"(b[0]), "r"(b[1]));
}
union U16x8 { unsigned short s[8]; uint4 v; };
union U16x4 { unsigned short s[4]; uint2 v; };
__device__ __forceinline__ void bsplit(float x, unsigned short& h, unsigned short& l) {
    __nv_bfloat16 bh = __float2bfloat16(x);
    __nv_bfloat16 bl = __float2bfloat16(x - __bfloat162float(bh));
    h = __bfloat16_as_ushort(bh); l = __bfloat16_as_ushort(bl);
}

// ---- prep kernels -------------------------------------------------------------
__global__ void k_gx(const float* __restrict__ in) {
    int b = blockIdx.x, tid = threadIdx.x;
    int c0 = tid * 8;
    const float4* xs = (const float4*)(in + (size_t)b * IN_COLS + 2560 + c0);
    float4 v0 = xs[0], v1 = xs[1];
    float x[8] = {v0.x, v0.y, v0.z, v0.w, v1.x, v1.y, v1.z, v1.w};
    U16x8 ph, pl;
    #pragma unroll
    for (int e = 0; e < 8; e++) {
        float g = (1.0f + 0.5f * expf(-fabsf(x[e]))) * x[e];
        bsplit(g, ph.s[e], pl.s[e]);
    }
    size_t o = ((size_t)b * N_DIM + c0) * 2;
    *(uint4*)(g_gxh + o) = ph.v;
    *(uint4*)(g_gxl + o) = pl.v;
}

__global__ void k_prep_A(const float* __restrict__ A) {
    int n = blockIdx.x, tid = threadIdx.x, c0 = tid * 8;
    const float4* xs = (const float4*)(A + (size_t)n * N_DIM + c0);
    float4 v0 = xs[0], v1 = xs[1];
    float x[8] = {v0.x, v0.y, v0.z, v0.w, v1.x, v1.y, v1.z, v1.w};
    U16x8 ph, pl;
    #pragma unroll
    for (int e = 0; e < 8; e++) bsplit(x[e], ph.s[e], pl.s[e]);
    size_t o = ((size_t)n * N_DIM + c0) * 2;
    *(uint4*)(g_Ah + o) = ph.v;
    *(uint4*)(g_Al + o) = pl.v;
}

__global__ void k_prep_W(const float* __restrict__ W) {  // Wt[n][k] = W[k][n]
    __shared__ float ts[32][33];
    int n0 = blockIdx.x * 32, k0 = blockIdx.y * 32, tid = threadIdx.x;
    #pragma unroll
    for (int i = 0; i < 4; i++) {
        int idx = tid + i * 256, kl = idx >> 5, nl = idx & 31;
        ts[kl][nl] = W[(size_t)(k0 + kl) * N_DIM + n0 + nl];
    }
    __syncthreads();
    int nl = tid >> 3, kq = (tid & 7) * 4;
    U16x4 ph, pl;
    #pragma unroll
    for (int j = 0; j < 4; j++) bsplit(ts[kq + j][nl], ph.s[j], pl.s[j]);
    size_t o = ((size_t)(n0 + nl) * M_DIM + k0 + kq) * 2;
    *(uint2*)(g_Wth + o) = ph.v;
    *(uint2*)(g_Wtl + o) = pl.v;
}

// ---- mma.sync GEMM core ---------------------------------------------------------
// CTA tile 128x128, 256 threads (warp grid 4m x 2n, warp tile 32x64), 1 CTA/SM.
// BK=64 chunks; 2 stages. Stage layout (pitch 144B): Ah[128] | Al | Bh | Bl.
// Register-level fragment double buffering across 4 ks-steps per chunk.
#define PITCH       144
#define ARR_BYTES   (128 * PITCH)     // 18432
#define STAGE_BYTES (4 * ARR_BYTES)   // 73728
#define GEMM_SMEM   (2 * STAGE_BYTES) // 147456

struct Frags { uint32_t ah[2][4]; uint32_t al[2][4]; uint32_t bh[8][2]; uint32_t bl[8][2]; };

__device__ __forceinline__ void frag_load(Frags& f, uint32_t sb, uint32_t a_off,
                                          uint32_t b_off, int ks) {
    #pragma unroll
    for (int i = 0; i < 2; i++) {
        uint32_t ad = sb + a_off + i * (16 * PITCH) + ks * 32;
        ldsm4(f.ah[i], ad);
        ldsm4(f.al[i], ad + ARR_BYTES);
    }
    #pragma unroll
    for (int j2 = 0; j2 < 4; j2++) {
        uint32_t bd = sb + 2 * ARR_BYTES + b_off + j2 * (16 * PITCH) + ks * 32;
        uint32_t t[4];
        ldsm4(t, bd);
        f.bh[2*j2][0] = t[0]; f.bh[2*j2][1] = t[1];
        f.bh[2*j2+1][0] = t[2]; f.bh[2*j2+1][1] = t[3];
        ldsm4(t, bd + ARR_BYTES);
        f.bl[2*j2][0] = t[0]; f.bl[2*j2][1] = t[1];
        f.bl[2*j2+1][0] = t[2]; f.bl[2*j2+1][1] = t[3];
    }
}

__device__ __forceinline__ void mma_block(float acc[2][8][4], const Frags& f) {
    #pragma unroll
    for (int i = 0; i < 2; i++)
        #pragma unroll
        for (int j = 0; j < 8; j++)
            mma16816(acc[i][j], f.ah[i], f.bh[j]);
    #pragma unroll
    for (int i = 0; i < 2; i++)
        #pragma unroll
        for (int j = 0; j < 8; j++)
            mma16816(acc[i][j], f.al[i], f.bh[j]);
    #pragma unroll
    for (int i = 0; i < 2; i++)
        #pragma unroll
        for (int j = 0; j < 8; j++)
            mma16816(acc[i][j], f.ah[i], f.bl[j]);
    // ll term dropped (~2^-16 relative)
}

// Load one BK=64 chunk into stage s. 16 cp.async per thread.
__device__ __forceinline__ void stage_load(
    uint32_t sbase, int s, int c,
    const unsigned char* Ah, const unsigned char* Al,
    const unsigned char* Bh, const unsigned char* Bl,
    int bm, int bn, int KLD, int tid)
{
    uint32_t sb = sbase + s * STAGE_BYTES;
    int r = tid >> 1, half = tid & 1;
    size_t kb = (size_t)c * 128 + half * 64;          // byte offset along K (bf16*2)
    uint32_t so = (uint32_t)r * PITCH + half * 64;
    size_t ga = (size_t)(bm + r) * KLD * 2 + kb;
    size_t gb = (size_t)(bn + r) * KLD * 2 + kb;
    #pragma unroll
    for (int i = 0; i < 4; i++) {
        cpa(sb + so + i * 16,                 Ah + ga + i * 16);
        cpa(sb + ARR_BYTES + so + i * 16,     Al + ga + i * 16);
        cpa(sb + 2 * ARR_BYTES + so + i * 16, Bh + gb + i * 16);
        cpa(sb + 3 * ARR_BYTES + so + i * 16, Bl + gb + i * 16);
    }
    asm volatile("cp.async.commit_group;" ::: "memory");
}

// NCHUNK: K/64 chunks. CF4: smuggled passthrough float4s per thread.
template<int NCHUNK, int KLD, int CF4>
__device__ __forceinline__ void mma_mainloop(
    uint32_t sbase,
    const unsigned char* Ah, const unsigned char* Al,
    const unsigned char* Bh, const unsigned char* Bl,
    int bm, int bn, float acc[2][8][4],
    const float4* __restrict__ csrc, float4* __restrict__ cdst)
{
    const int Q = (CF4 + NCHUNK - 1) / NCHUNK;
    int tid = threadIdx.x, lane = tid & 31, wid = tid >> 5;
    int m0 = (wid & 3) * 32, n0 = (wid >> 2) * 64;

    stage_load(sbase, 0, 0, Ah, Al, Bh, Bl, bm, bn, KLD, tid);
    stage_load(sbase, 1, 1, Ah, Al, Bh, Bl, bm, bn, KLD, tid);

    uint32_t a_off = (uint32_t)(m0 + (lane & 15)) * PITCH + (lane >> 4) * 16;
    uint32_t b_off = (uint32_t)(n0 + (lane & 7) + ((lane >> 4) & 1) * 8) * PITCH
                   + ((lane >> 3) & 1) * 16;

    asm volatile("cp.async.wait_group 1;" ::: "memory");  // chunk 0 landed
    __syncthreads();

    Frags fr[2];
    frag_load(fr[0], sbase, a_off, b_off, 0);

    for (int c = 0; c < NCHUNK; c++) {
        uint32_t sb = sbase + (c & 1) * STAGE_BYTES;
        // ks 0..2: prefetch next ks frags, MMA current
        frag_load(fr[1], sb, a_off, b_off, 1);
        mma_block(acc, fr[0]);
        frag_load(fr[0], sb, a_off, b_off, 2);
        mma_block(acc, fr[1]);
        frag_load(fr[1], sb, a_off, b_off, 3);
        mma_block(acc, fr[0]);
        // stage s fully register-resident; chunk c+1 must be complete & visible
        asm volatile("cp.async.wait_group 0;" ::: "memory");
        __syncthreads();
        if (c + 2 < NCHUNK)
            stage_load(sbase, c & 1, c + 2, Ah, Al, Bh, Bl, bm, bn, KLD, tid);
        // smuggled passthrough copy (pure DRAM work under tensor work)
        #pragma unroll
        for (int u = 0; u < Q; u++) {
            int idx = c * Q + u;
            if (idx < CF4) {
                int off = idx * 256 + tid;
                int row = off / 1152, col = off - row * 1152;
                cdst[row * 2176 + col] = csrc[row * 1152 + col];
            }
        }
        // ks3: prefetch chunk c+1 ks0 from other stage, MMA ks3
        frag_load(fr[0], sbase + ((c + 1) & 1) * STAGE_BYTES, a_off, b_off, 0);
        mma_block(acc, fr[1]);
    }
}

// GEMM1: res = y - gx @ A^T ; copies in-rows [cta*24, cta*24+24) to out
__global__ __launch_bounds__(256, 1) void k_gemm1_mma(const float* __restrict__ in,
                                                      float* __restrict__ out) {
    extern __shared__ unsigned char sm[];
    uint32_t sbase = smem_u32(sm);
    int bm = blockIdx.y * 128, bn = blockIdx.x * 128;
    int cta = blockIdx.y * gridDim.x + blockIdx.x;
    const float4* csrc = (const float4*)in + (size_t)cta * 24 * 1152;
    float4* cdst = (float4*)out + (size_t)cta * 24 * 2176;
    float acc[2][8][4] = {};
    mma_mainloop<32, N_DIM, 108>(sbase, g_gxh, g_gxl, g_Ah, g_Al, bm, bn, acc, csrc, cdst);

    int lane = threadIdx.x & 31, wid = threadIdx.x >> 5;
    int m0 = (wid & 3) * 32, n0 = (wid >> 2) * 64;
    #pragma unroll
    for (int i = 0; i < 2; i++) {
        int rb = bm + m0 + 16 * i + (lane >> 2);
        #pragma unroll
        for (int j = 0; j < 8; j++) {
            int col = bn + n0 + 8 * j + (lane & 3) * 2;
            #pragma unroll
            for (int h = 0; h < 2; h++) {
                int row = rb + 8 * h;
                float2 y = *(const float2*)(in + (size_t)row * IN_COLS + col);
                unsigned short h0, l0, h1, l1;
                bsplit(y.x - acc[i][j][2*h + 0], h0, l0);
                bsplit(y.y - acc[i][j][2*h + 1], h1, l1);
                size_t o = ((size_t)row * M_DIM + col) * 2;
                *(uint32_t*)(g_resh + o) = (uint32_t)h0 | ((uint32_t)h1 << 16);
                *(uint32_t*)(g_resl + o) = (uint32_t)l0 | ((uint32_t)l1 << 16);
            }
        }
    }
}

// GEMM2: zk = gx + 0.9 * res @ W ; copies in-rows [6144 + cta*2, +2) to out
__global__ __launch_bounds__(256, 1) void k_gemm2_mma(const float* __restrict__ in,
                                                      float* __restrict__ out) {
    extern __shared__ unsigned char sm[];
    uint32_t sbase = smem_u32(sm);
    int bm = blockIdx.y * 128, bn = blockIdx.x * 128;
    int cta = blockIdx.y * gridDim.x + blockIdx.x;
    const float4* csrc = (const float4*)in + ((size_t)6144 + cta * 2) * 1152;
    float4* cdst = (float4*)out + ((size_t)6144 + cta * 2) * 2176;
    float acc[2][8][4] = {};
    mma_mainloop<8, M_DIM, 9>(sbase, g_resh, g_resl, g_Wth, g_Wtl, bm, bn, acc, csrc, cdst);

    int lane = threadIdx.x & 31, wid = threadIdx.x >> 5;
    int m0 = (wid & 3) * 32, n0 = (wid >> 2) * 64;
    #pragma unroll
    for (int i = 0; i < 2; i++) {
        int rb = bm + m0 + 16 * i + (lane >> 2);
        #pragma unroll
        for (int j = 0; j < 8; j++) {
            int col = bn + n0 + 8 * j + (lane & 3) * 2;
            #pragma unroll
            for (int h = 0; h < 2; h++) {
                int row = rb + 8 * h;
                float2 xk = *(const float2*)(in + (size_t)row * IN_COLS + 2560 + col);
                float gx0 = (1.0f + 0.5f * expf(-fabsf(xk.x))) * xk.x;
                float gx1 = (1.0f + 0.5f * expf(-fabsf(xk.y))) * xk.y;
                float2 z;
                z.x = gx0 + 0.9f * acc[i][j][2*h + 0];
                z.y = gx1 + 0.9f * acc[i][j][2*h + 1];
                *(float2*)(g_zk + (size_t)row * N_DIM + col) = z;
            }
        }
    }
}

// ---- shrink: histogram k-th largest + gating (passthrough moved to GEMMs) ------
__global__ void k_shrink(const float* __restrict__ in, float* __restrict__ out) {
    int b = blockIdx.x, tid = threadIdx.x;
    __shared__ int hist[256];
    __shared__ unsigned s_pfx;
    __shared__ int s_k;

    const float* z = g_zk + (size_t)b * N_DIM;
    float zf[8]; unsigned vb[8];
    #pragma unroll
    for (int q = 0; q < 8; q++) {
        zf[q] = z[tid + q * 256];
        vb[q] = __float_as_uint(fabsf(zf[q]));
    }

    const int SHIFT[4] = {23, 15, 7, 0};
    const int HS[4]    = {31, 23, 15, 7};
    unsigned pfx = 0u; int k = KTH;
    #pragma unroll
    for (int lvl = 0; lvl < 4; lvl++) {
        int sh = SHIFT[lvl], hs = HS[lvl];
        hist[tid] = 0;
        __syncthreads();
        unsigned phi = pfx >> hs;
        #pragma unroll
        for (int q = 0; q < 8; q++)
            if ((vb[q] >> hs) == phi) atomicAdd(&hist[(vb[q] >> sh) & 0xFF], 1);
        __syncthreads();
        if (tid < 32) {
            int base = 255 - tid * 8, c[8], s = 0;
            #pragma unroll
            for (int j = 0; j < 8; j++) { c[j] = hist[base - j]; s += c[j]; }
            int incl = s;
            #pragma unroll
            for (int off = 1; off < 32; off <<= 1) {
                int t = __shfl_up_sync(0xffffffffu, incl, off);
                if (tid >= off) incl += t;
            }
            int excl = incl - s;
            if (excl < k && incl >= k) {
                int kk = k - excl, bin = base;
                #pragma unroll
                for (int j = 0; j < 8; j++) {
                    if (kk <= c[j]) { bin = base - j; break; }
                    kk -= c[j];
                }
                s_pfx = pfx | ((unsigned)bin << sh);
                s_k = kk;
            }
        }
        __syncthreads();
        pfx = s_pfx; k = s_k;
        __syncthreads();
    }
    float thres = __uint_as_float(pfx);

    const float* row_in = in + (size_t)b * IN_COLS;
    float* crow = out + (size_t)b * OUT_COLS + IN_COLS;
    float* orow = crow + N_DIM;
    #pragma unroll
    for (int q = 0; q < 8; q++) {
        int i = tid + q * 256;
        float zv = zf[q], az = __uint_as_float(vb[q]);
        float ind = (az > THETA && az > thres) ? 1.0f : 0.0f;
        float ci = 1.0f - ind;
        float soft = copysignf(fmaxf(az * ci - THETA, 0.0f), zv);
        float xt = ind * zv + soft;
        float xkv = row_in[2560 + i], cprv = row_in[512 + i];
        float p1 = 1.0f / (fabsf(xt - xkv) + 0.1f);
        float g = 1.0f - 0.5f * p1 * (THETA * cprv);
        crow[i] = ci;
        orow[i] = g * xt + (1.0f - g) * xkv;
    }
}

// ----------------------------------------------------------------------------------
extern "C" void kernel_launch(void* const* d_in, const int* in_sizes, int n_in,
                              void* d_out, int out_size) {
    (void)in_sizes; (void)n_in; (void)out_size;
    const float* in = (const float*)d_in[0];
    const float* A  = (const float*)d_in[1];
    const float* W  = (const float*)d_in[2];
    float* out = (float*)d_out;

    static int init = 0;
    if (!init) {
        cudaFuncSetAttribute(k_gemm1_mma, cudaFuncAttributeMaxDynamicSharedMemorySize, GEMM_SMEM);
        cudaFuncSetAttribute(k_gemm2_mma, cudaFuncAttributeMaxDynamicSharedMemorySize, GEMM_SMEM);
        init = 1;
    }

    k_gx<<<B_ROWS, 256>>>(in);
    k_prep_A<<<M_DIM, 256>>>(A);
    k_prep_W<<<dim3(N_DIM / 32, M_DIM / 32), 256>>>(W);
    k_gemm1_mma<<<dim3(M_DIM / 128, B_ROWS / 128), 256, GEMM_SMEM>>>(in, out);
    k_gemm2_mma<<<dim3(N_DIM / 128, B_ROWS / 128), 256, GEMM_SMEM>>>(in, out);
    k_shrink<<<B_ROWS, 256>>>(in, out);
}

// round 16
// speedup vs baseline: 1.2768x; 1.2768x over previous
#include <cuda_runtime.h>
#include <cuda_bf16.h>
#include <math.h>
#include <stdint.h>

#define B_ROWS   8192
#define M_DIM    512
#define N_DIM    2048
#define IN_COLS  4608
#define OUT_COLS 8704
#define THETA    0.1f
#define KTH      103

// ---- scratch: planar bf16 hi/lo operands -----------------------------------
__device__ __align__(16) unsigned char g_gxh [33554432]; // 8192x2048 bf16
__device__ __align__(16) unsigned char g_gxl [33554432];
__device__ __align__(16) unsigned char g_Ah  [2097152];  // 512x2048
__device__ __align__(16) unsigned char g_Al  [2097152];
__device__ __align__(16) unsigned char g_Wth [2097152];  // Wt: 2048x512
__device__ __align__(16) unsigned char g_Wtl [2097152];
__device__ __align__(16) unsigned char g_resh[8388608];  // 8192x512
__device__ __align__(16) unsigned char g_resl[8388608];
__device__ float g_zk[(size_t)B_ROWS * N_DIM];

// ---- helpers ----------------------------------------------------------------
__device__ __forceinline__ uint32_t smem_u32(const void* p) {
    uint32_t a;
    asm("{ .reg .u64 t; cvta.to.shared.u64 t, %1; cvt.u32.u64 %0, t; }" : "=r"(a) : "l"(p));
    return a;
}
__device__ __forceinline__ void cpa(uint32_t dst, const void* src) {
    asm volatile("cp.async.cg.shared.global [%0], [%1], 16;" :: "r"(dst), "l"(src));
}
__device__ __forceinline__ void ldsm4(uint32_t* r, uint32_t a) {
    asm volatile("ldmatrix.sync.aligned.m8n8.x4.shared.b16 {%0,%1,%2,%3}, [%4];"
                 : "=r"(r[0]), "=r"(r[1]), "=r"(r[2]), "=r"(r[3]) : "r"(a));
}
__device__ __forceinline__ void mma16816(float* c, const uint32_t* a, const uint32_t* b) {
    asm volatile(
        "mma.sync.aligned.m16n8k16.row.col.f32.bf16.bf16.f32 "
        "{%0,%1,%2,%3}, {%4,%5,%6,%7}, {%8,%9}, {%0,%1,%2,%3};"
        : "+f"(c[0]), "+f"(c[1]), "+f"(c[2]), "+f"(c[3])
        : "r"(a[0]), "r"(a[1]), "r"(a[2]), "r"(a[3]), "r"(b[0]), "r"(b[1]));
}
union U16x8 { unsigned short s[8]; uint4 v; };
union U16x4 { unsigned short s[4]; uint2 v; };
__device__ __forceinline__ void bsplit(float x, unsigned short& h, unsigned short& l) {
    __nv_bfloat16 bh = __float2bfloat16(x);
    __nv_bfloat16 bl = __float2bfloat16(x - __bfloat162float(bh));
    h = __bfloat16_as_ushort(bh); l = __bfloat16_as_ushort(bl);
}

// ---- prep kernels -------------------------------------------------------------
__global__ void k_gx(const float* __restrict__ in) {
    int b = blockIdx.x, tid = threadIdx.x;
    int c0 = tid * 8;
    const float4* xs = (const float4*)(in + (size_t)b * IN_COLS + 2560 + c0);
    float4 v0 = xs[0], v1 = xs[1];
    float x[8] = {v0.x, v0.y, v0.z, v0.w, v1.x, v1.y, v1.z, v1.w};
    U16x8 ph, pl;
    #pragma unroll
    for (int e = 0; e < 8; e++) {
        float g = (1.0f + 0.5f * expf(-fabsf(x[e]))) * x[e];
        bsplit(g, ph.s[e], pl.s[e]);
    }
    size_t o = ((size_t)b * N_DIM + c0) * 2;
    *(uint4*)(g_gxh + o) = ph.v;
    *(uint4*)(g_gxl + o) = pl.v;
}

__global__ void k_prep_A(const float* __restrict__ A) {
    int n = blockIdx.x, tid = threadIdx.x, c0 = tid * 8;
    const float4* xs = (const float4*)(A + (size_t)n * N_DIM + c0);
    float4 v0 = xs[0], v1 = xs[1];
    float x[8] = {v0.x, v0.y, v0.z, v0.w, v1.x, v1.y, v1.z, v1.w};
    U16x8 ph, pl;
    #pragma unroll
    for (int e = 0; e < 8; e++) bsplit(x[e], ph.s[e], pl.s[e]);
    size_t o = ((size_t)n * N_DIM + c0) * 2;
    *(uint4*)(g_Ah + o) = ph.v;
    *(uint4*)(g_Al + o) = pl.v;
}

__global__ void k_prep_W(const float* __restrict__ W) {  // Wt[n][k] = W[k][n]
    __shared__ float ts[32][33];
    int n0 = blockIdx.x * 32, k0 = blockIdx.y * 32, tid = threadIdx.x;
    #pragma unroll
    for (int i = 0; i < 4; i++) {
        int idx = tid + i * 256, kl = idx >> 5, nl = idx & 31;
        ts[kl][nl] = W[(size_t)(k0 + kl) * N_DIM + n0 + nl];
    }
    __syncthreads();
    int nl = tid >> 3, kq = (tid & 7) * 4;
    U16x4 ph, pl;
    #pragma unroll
    for (int j = 0; j < 4; j++) bsplit(ts[kq + j][nl], ph.s[j], pl.s[j]);
    size_t o = ((size_t)(n0 + nl) * M_DIM + k0 + kq) * 2;
    *(uint2*)(g_Wth + o) = ph.v;
    *(uint2*)(g_Wtl + o) = pl.v;
}

// ---- mma.sync GEMM core ---------------------------------------------------------
// CTA tile 128x128, 256 threads (warp grid 4m x 2n, warp tile 32x64), 1 CTA/SM.
// 4 stages x 40960B: Ah[128][40] | Al | Bh | Bl (80B pitch).
// Register-level fragment double buffering: MMA operands always one block ahead.
#define STAGE_BYTES 40960
#define GEMM_SMEM   (4 * STAGE_BYTES)

struct Frags { uint32_t ah[2][4]; uint32_t al[2][4]; uint32_t bh[8][2]; uint32_t bl[8][2]; };

__device__ __forceinline__ void frag_load(Frags& f, uint32_t sb, uint32_t a_off,
                                          uint32_t b_off, int ks) {
    #pragma unroll
    for (int i = 0; i < 2; i++) {
        uint32_t ad = sb + a_off + i * (16 * 80) + ks * 32;
        ldsm4(f.ah[i], ad);
        ldsm4(f.al[i], ad + 10240);
    }
    #pragma unroll
    for (int j2 = 0; j2 < 4; j2++) {
        uint32_t bd = sb + 20480 + b_off + j2 * (16 * 80) + ks * 32;
        uint32_t t[4];
        ldsm4(t, bd);
        f.bh[2*j2][0] = t[0]; f.bh[2*j2][1] = t[1];
        f.bh[2*j2+1][0] = t[2]; f.bh[2*j2+1][1] = t[3];
        ldsm4(t, bd + 10240);
        f.bl[2*j2][0] = t[0]; f.bl[2*j2][1] = t[1];
        f.bl[2*j2+1][0] = t[2]; f.bl[2*j2+1][1] = t[3];
    }
}

__device__ __forceinline__ void mma_block(float acc[2][8][4], const Frags& f) {
    #pragma unroll
    for (int i = 0; i < 2; i++)
        #pragma unroll
        for (int j = 0; j < 8; j++)
            mma16816(acc[i][j], f.ah[i], f.bh[j]);
    #pragma unroll
    for (int i = 0; i < 2; i++)
        #pragma unroll
        for (int j = 0; j < 8; j++)
            mma16816(acc[i][j], f.al[i], f.bh[j]);
    #pragma unroll
    for (int i = 0; i < 2; i++)
        #pragma unroll
        for (int j = 0; j < 8; j++)
            mma16816(acc[i][j], f.ah[i], f.bl[j]);
    // ll term dropped (~2^-16 relative)
}

__device__ __forceinline__ void stage_load(
    uint32_t sbase, int s, int c,
    const unsigned char* Ah, const unsigned char* Al,
    const unsigned char* Bh, const unsigned char* Bl,
    int bm, int bn, int KLD, int tid)
{
    uint32_t sb = sbase + s * STAGE_BYTES;
    int r = tid >> 2, seg = tid & 3;
    size_t kb = ((size_t)c * 32 + seg * 8) * 2;
    #pragma unroll
    for (int p = 0; p < 2; p++) {
        int row = r + p * 64;
        size_t ga = (size_t)(bm + row) * KLD * 2 + kb;
        size_t gb = (size_t)(bn + row) * KLD * 2 + kb;
        uint32_t so = (uint32_t)row * 80 + seg * 16;
        cpa(sb + so,         Ah + ga);
        cpa(sb + 10240 + so, Al + ga);
        cpa(sb + 20480 + so, Bh + gb);
        cpa(sb + 30720 + so, Bl + gb);
    }
    asm volatile("cp.async.commit_group;" ::: "memory");
}

template<int NCHUNK, int KLD>
__device__ __forceinline__ void mma_mainloop(
    uint32_t sbase,
    const unsigned char* Ah, const unsigned char* Al,
    const unsigned char* Bh, const unsigned char* Bl,
    int bm, int bn, float acc[2][8][4])
{
    int tid = threadIdx.x, lane = tid & 31, wid = tid >> 5;
    int m0 = (wid & 3) * 32, n0 = (wid >> 2) * 64;

    stage_load(sbase, 0, 0, Ah, Al, Bh, Bl, bm, bn, KLD, tid);
    stage_load(sbase, 1, 1, Ah, Al, Bh, Bl, bm, bn, KLD, tid);
    stage_load(sbase, 2, 2, Ah, Al, Bh, Bl, bm, bn, KLD, tid);
    stage_load(sbase, 3, 3, Ah, Al, Bh, Bl, bm, bn, KLD, tid);

    uint32_t a_off = (uint32_t)(m0 + (lane & 15)) * 80 + (lane >> 4) * 16;
    uint32_t b_off = (uint32_t)(n0 + (lane & 7) + ((lane >> 4) & 1) * 8) * 80
                   + ((lane >> 3) & 1) * 16;

    asm volatile("cp.async.wait_group 3;" ::: "memory");   // chunk 0 landed
    __syncthreads();

    Frags fr[2];
    frag_load(fr[0], sbase, a_off, b_off, 0);   // chunk 0, ks 0

    for (int c = 0; c < NCHUNK; c++) {
        int s = c & 3;
        uint32_t sb = sbase + s * STAGE_BYTES;
        // --- ks = 0: prefetch ks1 frags (last read of stage s), then MMA ks0
        frag_load(fr[1], sb, a_off, b_off, 1);
        mma_block(acc, fr[0]);
        // barrier hidden under the ks0 MMA queue; guarantees chunk c+1 resident
        asm volatile("cp.async.wait_group 2;" ::: "memory");
        __syncthreads();
        // refill stage s with chunk c+4 (all readers of s are done)
        if (c + 4 < NCHUNK)
            stage_load(sbase, s, c + 4, Ah, Al, Bh, Bl, bm, bn, KLD, tid);
        else
            asm volatile("cp.async.commit_group;" ::: "memory");
        // --- ks = 1: prefetch next chunk ks0 frags from stage c+1, then MMA ks1
        frag_load(fr[0], sbase + ((c + 1) & 3) * STAGE_BYTES, a_off, b_off, 0);
        mma_block(acc, fr[1]);
    }
}

// GEMM1: res = y - gx @ A^T ; writes res split bf16 hi/lo [8192,512]
__global__ __launch_bounds__(256, 1) void k_gemm1_mma(const float* __restrict__ in) {
    extern __shared__ unsigned char sm[];
    uint32_t sbase = smem_u32(sm);
    int bm = blockIdx.y * 128, bn = blockIdx.x * 128;
    float acc[2][8][4] = {};
    mma_mainloop<64, N_DIM>(sbase, g_gxh, g_gxl, g_Ah, g_Al, bm, bn, acc);

    int lane = threadIdx.x & 31, wid = threadIdx.x >> 5;
    int m0 = (wid & 3) * 32, n0 = (wid >> 2) * 64;
    #pragma unroll
    for (int i = 0; i < 2; i++) {
        int rb = bm + m0 + 16 * i + (lane >> 2);
        #pragma unroll
        for (int j = 0; j < 8; j++) {
            int col = bn + n0 + 8 * j + (lane & 3) * 2;
            #pragma unroll
            for (int h = 0; h < 2; h++) {
                int row = rb + 8 * h;
                float2 y = *(const float2*)(in + (size_t)row * IN_COLS + col);
                unsigned short h0, l0, h1, l1;
                bsplit(y.x - acc[i][j][2*h + 0], h0, l0);
                bsplit(y.y - acc[i][j][2*h + 1], h1, l1);
                size_t o = ((size_t)row * M_DIM + col) * 2;
                *(uint32_t*)(g_resh + o) = (uint32_t)h0 | ((uint32_t)h1 << 16);
                *(uint32_t*)(g_resl + o) = (uint32_t)l0 | ((uint32_t)l1 << 16);
            }
        }
    }
}

// GEMM2: zk = gx + 0.9 * res @ W ; writes zk fp32 [8192,2048]
__global__ __launch_bounds__(256, 1) void k_gemm2_mma(const float* __restrict__ in) {
    extern __shared__ unsigned char sm[];
    uint32_t sbase = smem_u32(sm);
    int bm = blockIdx.y * 128, bn = blockIdx.x * 128;
    float acc[2][8][4] = {};
    mma_mainloop<16, M_DIM>(sbase, g_resh, g_resl, g_Wth, g_Wtl, bm, bn, acc);

    int lane = threadIdx.x & 31, wid = threadIdx.x >> 5;
    int m0 = (wid & 3) * 32, n0 = (wid >> 2) * 64;
    #pragma unroll
    for (int i = 0; i < 2; i++) {
        int rb = bm + m0 + 16 * i + (lane >> 2);
        #pragma unroll
        for (int j = 0; j < 8; j++) {
            int col = bn + n0 + 8 * j + (lane & 3) * 2;
            #pragma unroll
            for (int h = 0; h < 2; h++) {
                int row = rb + 8 * h;
                float2 xk = *(const float2*)(in + (size_t)row * IN_COLS + 2560 + col);
                float gx0 = (1.0f + 0.5f * expf(-fabsf(xk.x))) * xk.x;
                float gx1 = (1.0f + 0.5f * expf(-fabsf(xk.y))) * xk.y;
                float2 z;
                z.x = gx0 + 0.9f * acc[i][j][2*h + 0];
                z.y = gx1 + 0.9f * acc[i][j][2*h + 1];
                *(float2*)(g_zk + (size_t)row * N_DIM + col) = z;
            }
        }
    }
}

// ---- shrink: histogram k-th largest + gating + fused input passthrough ---------
__global__ void k_shrink(const float* __restrict__ in, float* __restrict__ out) {
    int b = blockIdx.x, tid = threadIdx.x;
    __shared__ int hist[256];
    __shared__ unsigned s_pfx;
    __shared__ int s_k;

    const float* z = g_zk + (size_t)b * N_DIM;
    float zf[8]; unsigned vb[8];
    #pragma unroll
    for (int q = 0; q < 8; q++) {
        zf[q] = z[tid + q * 256];
        vb[q] = __float_as_uint(fabsf(zf[q]));
    }

    const int SHIFT[4] = {23, 15, 7, 0};
    const int HS[4]    = {31, 23, 15, 7};
    unsigned pfx = 0u; int k = KTH;
    #pragma unroll
    for (int lvl = 0; lvl < 4; lvl++) {
        int sh = SHIFT[lvl], hs = HS[lvl];
        hist[tid] = 0;
        __syncthreads();
        unsigned phi = pfx >> hs;
        #pragma unroll
        for (int q = 0; q < 8; q++)
            if ((vb[q] >> hs) == phi) atomicAdd(&hist[(vb[q] >> sh) & 0xFF], 1);
        __syncthreads();
        if (tid < 32) {
            int base = 255 - tid * 8, c[8], s = 0;
            #pragma unroll
            for (int j = 0; j < 8; j++) { c[j] = hist[base - j]; s += c[j]; }
            int incl = s;
            #pragma unroll
            for (int off = 1; off < 32; off <<= 1) {
                int t = __shfl_up_sync(0xffffffffu, incl, off);
                if (tid >= off) incl += t;
            }
            int excl = incl - s;
            if (excl < k && incl >= k) {
                int kk = k - excl, bin = base;
                #pragma unroll
                for (int j = 0; j < 8; j++) {
                    if (kk <= c[j]) { bin = base - j; break; }
                    kk -= c[j];
                }
                s_pfx = pfx | ((unsigned)bin << sh);
                s_k = kk;
            }
        }
        __syncthreads();
        pfx = s_pfx; k = s_k;
        __syncthreads();
    }
    float thres = __uint_as_float(pfx);

    const float* row_in = in + (size_t)b * IN_COLS;
    float* crow = out + (size_t)b * OUT_COLS + IN_COLS;
    float* orow = crow + N_DIM;
    #pragma unroll
    for (int q = 0; q < 8; q++) {
        int i = tid + q * 256;
        float zv = zf[q], az = __uint_as_float(vb[q]);
        float ind = (az > THETA && az > thres) ? 1.0f : 0.0f;
        float ci = 1.0f - ind;
        float soft = copysignf(fmaxf(az * ci - THETA, 0.0f), zv);
        float xt = ind * zv + soft;
        float xkv = row_in[2560 + i], cprv = row_in[512 + i];
        float p1 = 1.0f / (fabsf(xt - xkv) + 0.1f);
        float g = 1.0f - 0.5f * p1 * (THETA * cprv);
        crow[i] = ci;
        orow[i] = g * xt + (1.0f - g) * xkv;
    }

    // fused passthrough: out[:, :4608] = in
    const float4* src = (const float4*)row_in;
    float4* dst = (float4*)(out + (size_t)b * OUT_COLS);
    #pragma unroll 2
    for (int i = tid; i < IN_COLS / 4; i += 256) dst[i] = src[i];
}

// ----------------------------------------------------------------------------------
extern "C" void kernel_launch(void* const* d_in, const int* in_sizes, int n_in,
                              void* d_out, int out_size) {
    (void)in_sizes; (void)n_in; (void)out_size;
    const float* in = (const float*)d_in[0];
    const float* A  = (const float*)d_in[1];
    const float* W  = (const float*)d_in[2];
    float* out = (float*)d_out;

    static int init = 0;
    if (!init) {
        cudaFuncSetAttribute(k_gemm1_mma, cudaFuncAttributeMaxDynamicSharedMemorySize, GEMM_SMEM);
        cudaFuncSetAttribute(k_gemm2_mma, cudaFuncAttributeMaxDynamicSharedMemorySize, GEMM_SMEM);
        init = 1;
    }

    k_gx<<<B_ROWS, 256>>>(in);
    k_prep_A<<<M_DIM, 256>>>(A);
    k_prep_W<<<dim3(N_DIM / 32, M_DIM / 32), 256>>>(W);
    k_gemm1_mma<<<dim3(M_DIM / 128, B_ROWS / 128), 256, GEMM_SMEM>>>(in);
    k_gemm2_mma<<<dim3(N_DIM / 128, B_ROWS / 128), 256, GEMM_SMEM>>>(in);
    k_shrink<<<B_ROWS, 256>>>(in, out);
}